// round 14
// baseline (speedup 1.0000x reference)
#include <cuda_runtime.h>
#include <cuda_fp16.h>
#include <cstdint>

#define NTOK 8192
#define DIM  1024
#define NEXP 8
#define HID  4096
#define PADTOK (NTOK + 128)

// ===================== helpers =====================
__device__ __forceinline__ uint32_t smem_u32(const void* p) {
    uint32_t a;
    asm("{ .reg .u64 t; cvta.to.shared.u64 t, %1; cvt.u32.u64 %0, t; }" : "=r"(a) : "l"(p));
    return a;
}
__device__ __forceinline__ void cp16(uint32_t dst, const void* src) {
    asm volatile("cp.async.cg.shared.global [%0], [%1], 16;" :: "r"(dst), "l"(src) : "memory");
}
#define CP_COMMIT() asm volatile("cp.async.commit_group;" ::: "memory")
#define CP_WAIT1()  asm volatile("cp.async.wait_group 1;" ::: "memory")
#define CP_WAIT0()  asm volatile("cp.async.wait_group 0;" ::: "memory")

__device__ __forceinline__ void ldsm4(uint32_t& r0, uint32_t& r1, uint32_t& r2, uint32_t& r3,
                                      uint32_t addr) {
    asm volatile("ldmatrix.sync.aligned.m8n8.x4.shared.b16 {%0,%1,%2,%3}, [%4];"
                 : "=r"(r0), "=r"(r1), "=r"(r2), "=r"(r3) : "r"(addr));
}
__device__ __forceinline__ void mma16816(float& c0, float& c1, float& c2, float& c3,
                                         uint32_t a0, uint32_t a1, uint32_t a2, uint32_t a3,
                                         uint32_t b0, uint32_t b1) {
    asm volatile(
        "mma.sync.aligned.m16n8k16.row.col.f32.f16.f16.f32 "
        "{%0,%1,%2,%3}, {%4,%5,%6,%7}, {%8,%9}, {%0,%1,%2,%3};"
        : "+f"(c0), "+f"(c1), "+f"(c2), "+f"(c3)
        : "r"(a0), "r"(a1), "r"(a2), "r"(a3), "r"(b0), "r"(b1));
}

// ===================== device scratch =====================
__device__ int g_top1[NTOK];
__device__ int g_cnt[NEXP];
__device__ int g_cnt2[NEXP];
__device__ int g_off[NEXP];
__device__ int g_perm[NTOK];

__device__ __half g_x16[(size_t)NTOK * DIM];        // x fp16, TOKEN order
__device__ __half g_h[(size_t)PADTOK * HID];        // hidden, fp16, slot order
__device__ __half g_w1[(size_t)NEXP * HID * DIM];   // [e][n(HID)][k(DIM)]
__device__ __half g_w2[(size_t)NEXP * DIM * HID];   // [e][n(DIM)][k(HID)]

// ===================== conv tile bodies (32x32 transpose fp32->fp16) =====================
// 256-thread version (ty 0..7, stride 8)
__device__ __forceinline__ void conv_tile256(const float* __restrict__ src, __half* __restrict__ dst,
                                             int R, int C, int e, int r0, int c0) {
    __shared__ float tile[32][33];
    const int tx = threadIdx.x & 31;
    const int ty = threadIdx.x >> 5;   // 0..7
    const float* s = src + ((size_t)e * R + r0) * C + c0;
#pragma unroll
    for (int j = ty; j < 32; j += 8)
        tile[j][tx] = s[(size_t)j * C + tx];
    __syncthreads();
    __half* o = dst + ((size_t)e * C + c0) * R + r0;
#pragma unroll
    for (int j = ty; j < 32; j += 8)
        o[(size_t)j * R + tx] = __float2half_rn(tile[tx][j]);
}

// 128-thread version (ty 0..3, stride 4) — used inside the GEMM1 launch
__device__ __forceinline__ void conv_tile128(const float* __restrict__ src, __half* __restrict__ dst,
                                             int R, int C, int e, int r0, int c0) {
    __shared__ float tile[32][33];
    const int tx = threadIdx.x & 31;
    const int ty = threadIdx.x >> 5;   // 0..3
    const float* s = src + ((size_t)e * R + r0) * C + c0;
#pragma unroll
    for (int j = ty; j < 32; j += 4)
        tile[j][tx] = s[(size_t)j * C + tx];
    __syncthreads();
    __half* o = dst + ((size_t)e * C + c0) * R + r0;
#pragma unroll
    for (int j = ty; j < 32; j += 4)
        o[(size_t)j * R + tx] = __float2half_rn(tile[tx][j]);
}

// ===================== launch 0: gate (+x16) fused with conv_w1 (R9-exact) ==========
__global__ __launch_bounds__(256)
void gate_convw1_kernel(const float* __restrict__ x,
                        const float* __restrict__ gw,
                        const float* __restrict__ gb,
                        const float* __restrict__ w1) {
    const int b = blockIdx.x;
    if (b >= 1024) {
        int cb = b - 1024;                 // 0..32767
        int e  = cb >> 12;
        int r  = cb & 4095;
        int c0 = (r & 127) * 32;           // HID tile col
        int r0 = (r >> 7) * 32;            // DIM tile row
        conv_tile256(w1, g_w1, DIM, HID, e, r0, c0);
        return;
    }
    int wid  = threadIdx.x >> 5;
    int lane = threadIdx.x & 31;
    int tok  = b * 8 + wid;
    const float* xr = x + (size_t)tok * DIM;
    __half* xo = g_x16 + (size_t)tok * DIM;
    float acc[NEXP];
#pragma unroll
    for (int e = 0; e < NEXP; e++) acc[e] = 0.f;
    for (int d = lane; d < DIM; d += 32) {
        float xv = xr[d];
        xo[d] = __float2half_rn(xv);
        const float4* g4 = reinterpret_cast<const float4*>(gw + (size_t)d * NEXP);
        float4 g0 = g4[0], g1 = g4[1];
        acc[0] += xv * g0.x; acc[1] += xv * g0.y; acc[2] += xv * g0.z; acc[3] += xv * g0.w;
        acc[4] += xv * g1.x; acc[5] += xv * g1.y; acc[6] += xv * g1.z; acc[7] += xv * g1.w;
    }
#pragma unroll
    for (int e = 0; e < NEXP; e++) {
#pragma unroll
        for (int o = 16; o > 0; o >>= 1) acc[e] += __shfl_xor_sync(0xffffffffu, acc[e], o);
    }
    if (lane == 0) {
        int best = 0; float bv = acc[0] + gb[0];
#pragma unroll
        for (int e = 1; e < NEXP; e++) {
            float v = acc[e] + gb[e];
            if (v > bv) { bv = v; best = e; }
        }
        g_top1[tok] = best;
    }
}

// ===================== launch 1: histogram + scan (1 block) =====================
__global__ void hist_kernel() {
    __shared__ int cnt[NEXP];
    const int tid = threadIdx.x;
    if (tid < NEXP) cnt[tid] = 0;
    __syncthreads();
    int local[NEXP];
#pragma unroll
    for (int e = 0; e < NEXP; e++) local[e] = 0;
    for (int i = tid; i < NTOK; i += 1024) {
        int v = g_top1[i];
#pragma unroll
        for (int e = 0; e < NEXP; e++) local[e] += (v == e);
    }
#pragma unroll
    for (int e = 0; e < NEXP; e++) {
#pragma unroll
        for (int o = 16; o > 0; o >>= 1) local[e] += __shfl_xor_sync(0xffffffffu, local[e], o);
        if ((tid & 31) == 0 && local[e]) atomicAdd(&cnt[e], local[e]);
    }
    __syncthreads();
    if (tid == 0) {
        int off = 0;
        for (int e = 0; e < NEXP; e++) { g_off[e] = off; g_cnt[e] = cnt[e]; off += cnt[e]; }
    }
    if (tid < NEXP) g_cnt2[tid] = 0;
}

// ===================== launch 2: scatter (only) =====================
__global__ __launch_bounds__(256)
void scatter_kernel() {
    int n = blockIdx.x * 256 + threadIdx.x;
    int e = g_top1[n];
    int p = atomicAdd(&g_cnt2[e], 1);
    g_perm[g_off[e] + p] = n;
}

// ===================== GEMM core: CTA 128x128, 4 warps 2x2, warp tile 64x64 =====================
// GEMM1 additionally carries conv_w2 tile-blocks at blockIdx.z >= NEXP: they are
// scheduled after the GEMM blocks and overlap GEMM1's tensor-bound execution
// (GEMM1 DRAM util is ~8%, so the conv's pure-DRAM work rides nearly free).
// GEMM2 (launched after the full GEMM1 grid completes) then sees g_w2 ready.
#define AOFF 0
#define BOFF 16384
#define STAGE 32768
#define NSTAGE 3
#define CONVZ 16          // 16 extra z-slices x 2048 blocks = 32768 conv tiles

template<bool FIRST>
__global__ __launch_bounds__(128, 2)
void moe_gemm(const float* __restrict__ bias,
              const float* __restrict__ x,
              float* __restrict__ out,
              const float* __restrict__ w2f32) {
    constexpr int KDIM = FIRST ? DIM : HID;
    constexpr int NDIM = FIRST ? HID : DIM;
    constexpr int NKC  = KDIM / 64;

    if (FIRST && blockIdx.z >= NEXP) {
        int cb = (blockIdx.z - NEXP) * 2048 + blockIdx.y * 32 + blockIdx.x;  // 0..32767
        int e  = cb >> 12;
        int r  = cb & 4095;
        int c0 = (r & 31) * 32;            // DIM tile col
        int r0 = (r >> 5) * 32;            // HID tile row
        conv_tile128(w2f32, g_w2, HID, DIM, e, r0, c0);
        return;
    }

    const int e  = blockIdx.z;
    const int Me = g_cnt[e];
    const int m0 = blockIdx.y * 128;
    if (m0 >= Me) return;
    const int off = g_off[e];
    const int n0  = blockIdx.x * 128;

    const __half* A = FIRST ? g_x16 : g_h;
    const __half* W = (FIRST ? g_w1 : g_w2) + (size_t)e * NDIM * KDIM;

    extern __shared__ char smem[];
    const uint32_t sb = smem_u32(smem);
    __shared__ int s_perm[128];

    const int tid  = threadIdx.x;
    const int lane = tid & 31;
    const int wid  = tid >> 5;
    const int wrow = wid & 1;
    const int wcol = wid >> 1;

    {
        int r = m0 + tid;
        if (r >= Me) r = Me - 1;
        s_perm[tid] = g_perm[off + r];
    }
    __syncthreads();

    auto issue_loads = [&](int chunk) {
        const uint32_t base = sb + (chunk % NSTAGE) * STAGE;
        const int k0 = chunk * 64;
#pragma unroll
        for (int w = 0; w < 8; w++) {
            int idx = w * 128 + tid;
            int row = idx >> 3;
            int c8  = idx & 7;
            uint32_t sw = (uint32_t)(row * 128 + ((c8 * 16) ^ ((row & 7) << 4)));
            const __half* asrc;
            if (FIRST) asrc = A + (size_t)s_perm[row] * KDIM + k0 + c8 * 8;
            else       asrc = A + (size_t)(off + m0 + row) * KDIM + k0 + c8 * 8;
            cp16(base + AOFF + sw, asrc);
            cp16(base + BOFF + sw, W + (size_t)(n0 + row) * KDIM + k0 + c8 * 8);
        }
    };

    const int sel = lane >> 3;
    const int l7  = lane & 7;
    const uint32_t lxor = (uint32_t)(l7 << 4);
    uint32_t arow[4], brow[4];
#pragma unroll
    for (int mf = 0; mf < 4; mf++)
        arow[mf] = (uint32_t)((wrow * 64 + mf * 16 + (sel & 1) * 8 + l7) * 128);
#pragma unroll
    for (int nb = 0; nb < 4; nb++)
        brow[nb] = (uint32_t)((wcol * 64 + nb * 16 + (sel >> 1) * 8 + l7) * 128);
    const uint32_t acb = (uint32_t)((sel >> 1) * 16);
    const uint32_t bcb = (uint32_t)((sel & 1) * 16);

    float c[4][8][4];
#pragma unroll
    for (int i = 0; i < 4; i++)
#pragma unroll
        for (int j = 0; j < 8; j++)
#pragma unroll
            for (int r = 0; r < 4; r++) c[i][j][r] = 0.f;

    issue_loads(0); CP_COMMIT();
    issue_loads(1); CP_COMMIT();

#pragma unroll 1
    for (int i = 0; i < NKC; i++) {
        if (i < NKC - 1) { CP_WAIT1(); } else { CP_WAIT0(); }
        __syncthreads();                         // single barrier per chunk
        if (i + 2 < NKC) { issue_loads(i + 2); CP_COMMIT(); }

        const uint32_t base = sb + (i % NSTAGE) * STAGE;
#pragma unroll
        for (int kk = 0; kk < 4; kk++) {
            const uint32_t colA = (acb + kk * 32) ^ lxor;
            const uint32_t colB = (bcb + kk * 32) ^ lxor;

            uint32_t Af[4][4], Bf[4][4];
#pragma unroll
            for (int mf = 0; mf < 4; mf++)
                ldsm4(Af[mf][0], Af[mf][1], Af[mf][2], Af[mf][3], base + AOFF + arow[mf] + colA);
#pragma unroll
            for (int nb = 0; nb < 4; nb++)
                ldsm4(Bf[nb][0], Bf[nb][1], Bf[nb][2], Bf[nb][3], base + BOFF + brow[nb] + colB);
#pragma unroll
            for (int mf = 0; mf < 4; mf++)
#pragma unroll
                for (int nb = 0; nb < 4; nb++)
#pragma unroll
                    for (int h = 0; h < 2; h++)
                        mma16816(c[mf][nb*2+h][0], c[mf][nb*2+h][1], c[mf][nb*2+h][2], c[mf][nb*2+h][3],
                                 Af[mf][0], Af[mf][1], Af[mf][2], Af[mf][3],
                                 Bf[nb][2*h], Bf[nb][2*h+1]);
        }
    }

    const int gr = lane >> 2;
    const int gc = (lane & 3) * 2;
    const float* bs = bias + (size_t)e * NDIM;

#pragma unroll
    for (int mf = 0; mf < 4; mf++) {
#pragma unroll
        for (int half = 0; half < 2; half++) {
            const int ml = wrow * 64 + mf * 16 + half * 8 + gr;
            if (m0 + ml >= Me) continue;
            const int slot = off + m0 + ml;
#pragma unroll
            for (int nf = 0; nf < 8; nf++) {
                const int n = n0 + wcol * 64 + nf * 8 + gc;
                const float2 bv = *reinterpret_cast<const float2*>(bs + n);
                float v0 = c[mf][nf][half * 2 + 0] + bv.x;
                float v1 = c[mf][nf][half * 2 + 1] + bv.y;
                if (FIRST) {
                    v0 = fmaxf(v0, 0.f);
                    v1 = fmaxf(v1, 0.f);
                    *reinterpret_cast<__half2*>(g_h + (size_t)slot * HID + n) =
                        __half2(__float2half_rn(v0), __float2half_rn(v1));
                } else {
                    const int tok = s_perm[ml];
                    const float2 xv = *reinterpret_cast<const float2*>(x + (size_t)tok * DIM + n);
                    float2 ov = make_float2(v0 + xv.x, v1 + xv.y);
                    *reinterpret_cast<float2*>(out + (size_t)tok * DIM + n) = ov;
                }
            }
        }
    }
}

// ===================== launch =====================
extern "C" void kernel_launch(void* const* d_in, const int* in_sizes, int n_in,
                              void* d_out, int out_size) {
    const float* x  = (const float*)d_in[0];
    const float* gw = (const float*)d_in[1];
    const float* gb = (const float*)d_in[2];
    const float* w1 = (const float*)d_in[3];
    const float* b1 = (const float*)d_in[4];
    const float* w2 = (const float*)d_in[5];
    const float* b2 = (const float*)d_in[6];
    float* out = (float*)d_out;

    const int SMEM_BYTES = NSTAGE * STAGE;   // 96KB -> 2 CTAs/SM
    cudaFuncSetAttribute(moe_gemm<true>,  cudaFuncAttributeMaxDynamicSharedMemorySize, SMEM_BYTES);
    cudaFuncSetAttribute(moe_gemm<false>, cudaFuncAttributeMaxDynamicSharedMemorySize, SMEM_BYTES);

    // launch 0: gate + conv_w1 (independent blocks, run concurrently)
    gate_convw1_kernel<<<1024 + 32768, 256>>>(x, gw, gb, w1);
    // launch 1: histogram + scan
    hist_kernel<<<1, 1024>>>();
    // launch 2: scatter
    scatter_kernel<<<NTOK / 256, 256>>>();
    // launch 3: GEMM1 + conv_w2 (conv blocks ride GEMM1's spare DRAM bandwidth;
    //           GEMM2 starts only after this whole grid -> g_w2 ready)
    moe_gemm<true ><<<dim3(HID / 128, NTOK / 128, NEXP + CONVZ), 128, SMEM_BYTES>>>(b1, x, nullptr, w2);
    // launch 4: GEMM2
    moe_gemm<false><<<dim3(DIM / 128, NTOK / 128, NEXP), 128, SMEM_BYTES>>>(b2, x, out, nullptr);
}

// round 15
// speedup vs baseline: 1.6763x; 1.6763x over previous
#include <cuda_runtime.h>
#include <cuda_fp16.h>
#include <cstdint>

#define NTOK 8192
#define DIM  1024
#define NEXP 8
#define HID  4096
#define PADTOK (NTOK + 128)

// ===================== helpers =====================
__device__ __forceinline__ uint32_t smem_u32(const void* p) {
    uint32_t a;
    asm("{ .reg .u64 t; cvta.to.shared.u64 t, %1; cvt.u32.u64 %0, t; }" : "=r"(a) : "l"(p));
    return a;
}
__device__ __forceinline__ void cp16(uint32_t dst, const void* src) {
    asm volatile("cp.async.cg.shared.global [%0], [%1], 16;" :: "r"(dst), "l"(src) : "memory");
}
#define CP_COMMIT() asm volatile("cp.async.commit_group;" ::: "memory")
#define CP_WAIT1()  asm volatile("cp.async.wait_group 1;" ::: "memory")
#define CP_WAIT0()  asm volatile("cp.async.wait_group 0;" ::: "memory")

__device__ __forceinline__ void ldsm4(uint32_t& r0, uint32_t& r1, uint32_t& r2, uint32_t& r3,
                                      uint32_t addr) {
    asm volatile("ldmatrix.sync.aligned.m8n8.x4.shared.b16 {%0,%1,%2,%3}, [%4];"
                 : "=r"(r0), "=r"(r1), "=r"(r2), "=r"(r3) : "r"(addr));
}
__device__ __forceinline__ void mma16816(float& c0, float& c1, float& c2, float& c3,
                                         uint32_t a0, uint32_t a1, uint32_t a2, uint32_t a3,
                                         uint32_t b0, uint32_t b1) {
    asm volatile(
        "mma.sync.aligned.m16n8k16.row.col.f32.f16.f16.f32 "
        "{%0,%1,%2,%3}, {%4,%5,%6,%7}, {%8,%9}, {%0,%1,%2,%3};"
        : "+f"(c0), "+f"(c1), "+f"(c2), "+f"(c3)
        : "r"(a0), "r"(a1), "r"(a2), "r"(a3), "r"(b0), "r"(b1));
}

// ===================== device scratch =====================
__device__ int g_top1[NTOK];
__device__ int g_cnt[NEXP];
__device__ int g_cnt2[NEXP];
__device__ int g_off[NEXP];
__device__ int g_perm[NTOK];

__device__ __half g_x16[(size_t)NTOK * DIM];        // x fp16, TOKEN order
__device__ __half g_h[(size_t)PADTOK * HID];        // hidden, fp16, slot order
__device__ __half g_w1[(size_t)NEXP * HID * DIM];   // [e][n(HID)][k(DIM)]
__device__ __half g_w2[(size_t)NEXP * DIM * HID];   // [e][n(DIM)][k(HID)]

// ===================== conv tile body (32x32 transpose fp32->fp16) =====================
__device__ __forceinline__ void conv_tile(const float* __restrict__ src, __half* __restrict__ dst,
                                          int R, int C, int e, int r0, int c0) {
    __shared__ float tile[32][33];
    const int tx = threadIdx.x & 31;
    const int ty = threadIdx.x >> 5;   // 0..7
    const float* s = src + ((size_t)e * R + r0) * C + c0;
#pragma unroll
    for (int j = ty; j < 32; j += 8)
        tile[j][tx] = s[(size_t)j * C + tx];
    __syncthreads();
    __half* o = dst + ((size_t)e * C + c0) * R + r0;
#pragma unroll
    for (int j = ty; j < 32; j += 8)
        o[(size_t)j * R + tx] = __float2half_rn(tile[tx][j]);
}

// ===================== launch 0: gate (+x16) fused with conv_w1 =====================
// blocks [0,1024): gate; blocks [1024, 1024+32768): conv_w1 tiles
__global__ __launch_bounds__(256)
void gate_convw1_kernel(const float* __restrict__ x,
                        const float* __restrict__ gw,
                        const float* __restrict__ gb,
                        const float* __restrict__ w1) {
    const int b = blockIdx.x;
    if (b >= 1024) {
        int cb = b - 1024;                 // 0..32767
        int e  = cb >> 12;
        int r  = cb & 4095;
        int c0 = (r & 127) * 32;           // HID tile col
        int r0 = (r >> 7) * 32;            // DIM tile row
        conv_tile(w1, g_w1, DIM, HID, e, r0, c0);
        return;
    }
    int wid  = threadIdx.x >> 5;
    int lane = threadIdx.x & 31;
    int tok  = b * 8 + wid;
    const float* xr = x + (size_t)tok * DIM;
    __half* xo = g_x16 + (size_t)tok * DIM;
    float acc[NEXP];
#pragma unroll
    for (int e = 0; e < NEXP; e++) acc[e] = 0.f;
    for (int d = lane; d < DIM; d += 32) {
        float xv = xr[d];
        xo[d] = __float2half_rn(xv);
        const float4* g4 = reinterpret_cast<const float4*>(gw + (size_t)d * NEXP);
        float4 g0 = g4[0], g1 = g4[1];
        acc[0] += xv * g0.x; acc[1] += xv * g0.y; acc[2] += xv * g0.z; acc[3] += xv * g0.w;
        acc[4] += xv * g1.x; acc[5] += xv * g1.y; acc[6] += xv * g1.z; acc[7] += xv * g1.w;
    }
#pragma unroll
    for (int e = 0; e < NEXP; e++) {
#pragma unroll
        for (int o = 16; o > 0; o >>= 1) acc[e] += __shfl_xor_sync(0xffffffffu, acc[e], o);
    }
    if (lane == 0) {
        int best = 0; float bv = acc[0] + gb[0];
#pragma unroll
        for (int e = 1; e < NEXP; e++) {
            float v = acc[e] + gb[e];
            if (v > bv) { bv = v; best = e; }
        }
        g_top1[tok] = best;
    }
}

// ===================== launch 1: histogram + scan (1 block) =====================
__global__ void hist_kernel() {
    __shared__ int cnt[NEXP];
    const int tid = threadIdx.x;
    if (tid < NEXP) cnt[tid] = 0;
    __syncthreads();
    int local[NEXP];
#pragma unroll
    for (int e = 0; e < NEXP; e++) local[e] = 0;
    for (int i = tid; i < NTOK; i += 1024) {
        int v = g_top1[i];
#pragma unroll
        for (int e = 0; e < NEXP; e++) local[e] += (v == e);
    }
#pragma unroll
    for (int e = 0; e < NEXP; e++) {
#pragma unroll
        for (int o = 16; o > 0; o >>= 1) local[e] += __shfl_xor_sync(0xffffffffu, local[e], o);
        if ((tid & 31) == 0 && local[e]) atomicAdd(&cnt[e], local[e]);
    }
    __syncthreads();
    if (tid == 0) {
        int off = 0;
        for (int e = 0; e < NEXP; e++) { g_off[e] = off; g_cnt[e] = cnt[e]; off += cnt[e]; }
    }
    if (tid < NEXP) g_cnt2[tid] = 0;
}

// ===================== launch 2: scatter fused with conv_w2 =====================
// blocks [0,32): scatter; blocks [32, 32+32768): conv_w2 tiles
__global__ __launch_bounds__(256)
void scatter_convw2_kernel(const float* __restrict__ w2) {
    const int b = blockIdx.x;
    if (b >= 32) {
        int cb = b - 32;
        int e  = cb >> 12;
        int r  = cb & 4095;
        int c0 = (r & 31) * 32;            // DIM tile col
        int r0 = (r >> 5) * 32;            // HID tile row
        conv_tile(w2, g_w2, HID, DIM, e, r0, c0);
        return;
    }
    int n = b * 256 + threadIdx.x;
    int e = g_top1[n];
    int p = atomicAdd(&g_cnt2[e], 1);
    g_perm[g_off[e] + p] = n;
}

// ===================== GEMM core: CTA 128x128, 4 warps 2x2, warp tile 64x64 =====================
// Single __syncthreads per K-chunk: loads for chunk i+2 are issued AFTER the
// barrier that follows chunk i's arrival. Passing barrier i implies all warps
// completed chunk i-1's MMAs, so overwriting stage (i+2)%3 == (i-1)%3 is safe.
#define AOFF 0
#define BOFF 16384
#define STAGE 32768
#define NSTAGE 3

template<bool FIRST>
__global__ __launch_bounds__(128, 2)
void moe_gemm(const float* __restrict__ bias,
              const float* __restrict__ x,
              float* __restrict__ out) {
    constexpr int KDIM = FIRST ? DIM : HID;
    constexpr int NDIM = FIRST ? HID : DIM;
    constexpr int NKC  = KDIM / 64;

    const int e  = blockIdx.z;
    const int Me = g_cnt[e];
    const int m0 = blockIdx.y * 128;
    if (m0 >= Me) return;
    const int off = g_off[e];
    const int n0  = blockIdx.x * 128;

    const __half* A = FIRST ? g_x16 : g_h;
    const __half* W = (FIRST ? g_w1 : g_w2) + (size_t)e * NDIM * KDIM;

    extern __shared__ char smem[];
    const uint32_t sb = smem_u32(smem);
    __shared__ int s_perm[128];

    const int tid  = threadIdx.x;
    const int lane = tid & 31;
    const int wid  = tid >> 5;
    const int wrow = wid & 1;
    const int wcol = wid >> 1;

    {
        int r = m0 + tid;
        if (r >= Me) r = Me - 1;
        s_perm[tid] = g_perm[off + r];
    }
    __syncthreads();

    auto issue_loads = [&](int chunk) {
        const uint32_t base = sb + (chunk % NSTAGE) * STAGE;
        const int k0 = chunk * 64;
#pragma unroll
        for (int w = 0; w < 8; w++) {
            int idx = w * 128 + tid;
            int row = idx >> 3;
            int c8  = idx & 7;
            uint32_t sw = (uint32_t)(row * 128 + ((c8 * 16) ^ ((row & 7) << 4)));
            const __half* asrc;
            if (FIRST) asrc = A + (size_t)s_perm[row] * KDIM + k0 + c8 * 8;
            else       asrc = A + (size_t)(off + m0 + row) * KDIM + k0 + c8 * 8;
            cp16(base + AOFF + sw, asrc);
            cp16(base + BOFF + sw, W + (size_t)(n0 + row) * KDIM + k0 + c8 * 8);
        }
    };

    const int sel = lane >> 3;
    const int l7  = lane & 7;
    const uint32_t lxor = (uint32_t)(l7 << 4);
    uint32_t arow[4], brow[4];
#pragma unroll
    for (int mf = 0; mf < 4; mf++)
        arow[mf] = (uint32_t)((wrow * 64 + mf * 16 + (sel & 1) * 8 + l7) * 128);
#pragma unroll
    for (int nb = 0; nb < 4; nb++)
        brow[nb] = (uint32_t)((wcol * 64 + nb * 16 + (sel >> 1) * 8 + l7) * 128);
    const uint32_t acb = (uint32_t)((sel >> 1) * 16);
    const uint32_t bcb = (uint32_t)((sel & 1) * 16);

    float c[4][8][4];
#pragma unroll
    for (int i = 0; i < 4; i++)
#pragma unroll
        for (int j = 0; j < 8; j++)
#pragma unroll
            for (int r = 0; r < 4; r++) c[i][j][r] = 0.f;

    issue_loads(0); CP_COMMIT();
    issue_loads(1); CP_COMMIT();

#pragma unroll 1
    for (int i = 0; i < NKC; i++) {
        if (i < NKC - 1) { CP_WAIT1(); } else { CP_WAIT0(); }
        __syncthreads();                         // single barrier per chunk
        if (i + 2 < NKC) { issue_loads(i + 2); CP_COMMIT(); }

        const uint32_t base = sb + (i % NSTAGE) * STAGE;
#pragma unroll
        for (int kk = 0; kk < 4; kk++) {
            const uint32_t colA = (acb + kk * 32) ^ lxor;
            const uint32_t colB = (bcb + kk * 32) ^ lxor;

            uint32_t Af[4][4], Bf[4][4];
#pragma unroll
            for (int mf = 0; mf < 4; mf++)
                ldsm4(Af[mf][0], Af[mf][1], Af[mf][2], Af[mf][3], base + AOFF + arow[mf] + colA);
#pragma unroll
            for (int nb = 0; nb < 4; nb++)
                ldsm4(Bf[nb][0], Bf[nb][1], Bf[nb][2], Bf[nb][3], base + BOFF + brow[nb] + colB);
#pragma unroll
            for (int mf = 0; mf < 4; mf++)
#pragma unroll
                for (int nb = 0; nb < 4; nb++)
#pragma unroll
                    for (int h = 0; h < 2; h++)
                        mma16816(c[mf][nb*2+h][0], c[mf][nb*2+h][1], c[mf][nb*2+h][2], c[mf][nb*2+h][3],
                                 Af[mf][0], Af[mf][1], Af[mf][2], Af[mf][3],
                                 Bf[nb][2*h], Bf[nb][2*h+1]);
        }
    }

    const int gr = lane >> 2;
    const int gc = (lane & 3) * 2;
    const float* bs = bias + (size_t)e * NDIM;

#pragma unroll
    for (int mf = 0; mf < 4; mf++) {
#pragma unroll
        for (int half = 0; half < 2; half++) {
            const int ml = wrow * 64 + mf * 16 + half * 8 + gr;
            if (m0 + ml >= Me) continue;
            const int slot = off + m0 + ml;
#pragma unroll
            for (int nf = 0; nf < 8; nf++) {
                const int n = n0 + wcol * 64 + nf * 8 + gc;
                const float2 bv = *reinterpret_cast<const float2*>(bs + n);
                float v0 = c[mf][nf][half * 2 + 0] + bv.x;
                float v1 = c[mf][nf][half * 2 + 1] + bv.y;
                if (FIRST) {
                    v0 = fmaxf(v0, 0.f);
                    v1 = fmaxf(v1, 0.f);
                    *reinterpret_cast<__half2*>(g_h + (size_t)slot * HID + n) =
                        __half2(__float2half_rn(v0), __float2half_rn(v1));
                } else {
                    const int tok = s_perm[ml];
                    const float2 xv = *reinterpret_cast<const float2*>(x + (size_t)tok * DIM + n);
                    float2 ov = make_float2(v0 + xv.x, v1 + xv.y);
                    *reinterpret_cast<float2*>(out + (size_t)tok * DIM + n) = ov;
                }
            }
        }
    }
}

// ===================== launch =====================
extern "C" void kernel_launch(void* const* d_in, const int* in_sizes, int n_in,
                              void* d_out, int out_size) {
    const float* x  = (const float*)d_in[0];
    const float* gw = (const float*)d_in[1];
    const float* gb = (const float*)d_in[2];
    const float* w1 = (const float*)d_in[3];
    const float* b1 = (const float*)d_in[4];
    const float* w2 = (const float*)d_in[5];
    const float* b2 = (const float*)d_in[6];
    float* out = (float*)d_out;

    const int SMEM_BYTES = NSTAGE * STAGE;   // 96KB -> 2 CTAs/SM
    cudaFuncSetAttribute(moe_gemm<true>,  cudaFuncAttributeMaxDynamicSharedMemorySize, SMEM_BYTES);
    cudaFuncSetAttribute(moe_gemm<false>, cudaFuncAttributeMaxDynamicSharedMemorySize, SMEM_BYTES);

    // launch 0: gate + conv_w1 (independent blocks, run concurrently)
    gate_convw1_kernel<<<1024 + 32768, 256>>>(x, gw, gb, w1);
    // launch 1: histogram + scan
    hist_kernel<<<1, 1024>>>();
    // launch 2: scatter + conv_w2
    scatter_convw2_kernel<<<32 + 32768, 256>>>(w2);
    // launch 3: GEMM1
    moe_gemm<true ><<<dim3(HID / 128, NTOK / 128, NEXP), 128, SMEM_BYTES>>>(b1, x, nullptr);
    // launch 4: GEMM2
    moe_gemm<false><<<dim3(DIM / 128, NTOK / 128, NEXP), 128, SMEM_BYTES>>>(b2, x, out);
}

// round 17
// speedup vs baseline: 1.7565x; 1.0479x over previous
#include <cuda_runtime.h>
#include <cuda_fp16.h>
#include <cuda.h>
#include <cstdint>

#define NTOK 8192
#define DIM  1024
#define NEXP 8
#define HID  4096
#define PADTOK (NTOK + 128)

// ===================== helpers =====================
__device__ __forceinline__ uint32_t smem_u32(const void* p) {
    uint32_t a;
    asm("{ .reg .u64 t; cvta.to.shared.u64 t, %1; cvt.u32.u64 %0, t; }" : "=r"(a) : "l"(p));
    return a;
}
__device__ __forceinline__ void cp16(uint32_t dst, const void* src) {
    asm volatile("cp.async.cg.shared.global [%0], [%1], 16;" :: "r"(dst), "l"(src) : "memory");
}
#define CP_COMMIT() asm volatile("cp.async.commit_group;" ::: "memory")
#define CP_WAIT1()  asm volatile("cp.async.wait_group 1;" ::: "memory")
#define CP_WAIT0()  asm volatile("cp.async.wait_group 0;" ::: "memory")

__device__ __forceinline__ void ldsm4(uint32_t& r0, uint32_t& r1, uint32_t& r2, uint32_t& r3,
                                      uint32_t addr) {
    asm volatile("ldmatrix.sync.aligned.m8n8.x4.shared.b16 {%0,%1,%2,%3}, [%4];"
                 : "=r"(r0), "=r"(r1), "=r"(r2), "=r"(r3) : "r"(addr));
}
__device__ __forceinline__ void mma16816(float& c0, float& c1, float& c2, float& c3,
                                         uint32_t a0, uint32_t a1, uint32_t a2, uint32_t a3,
                                         uint32_t b0, uint32_t b1) {
    asm volatile(
        "mma.sync.aligned.m16n8k16.row.col.f32.f16.f16.f32 "
        "{%0,%1,%2,%3}, {%4,%5,%6,%7}, {%8,%9}, {%0,%1,%2,%3};"
        : "+f"(c0), "+f"(c1), "+f"(c2), "+f"(c3)
        : "r"(a0), "r"(a1), "r"(a2), "r"(a3), "r"(b0), "r"(b1));
}

// mbarrier + TMA
#define MBARRIER_INIT(mb, cnt) \
    asm volatile("mbarrier.init.shared.b64 [%0], %1;" :: "r"((uint32_t)(mb)), "r"((uint32_t)(cnt)) : "memory")
#define MBARRIER_EXPECT_TX(mb, bytes) \
    asm volatile("mbarrier.arrive.expect_tx.shared.b64 _, [%0], %1;" :: "r"((uint32_t)(mb)), "r"((uint32_t)(bytes)) : "memory")
#define MBARRIER_WAIT_PARITY(mb, par) do {                                            \
    uint32_t _m = (uint32_t)(mb); uint32_t _p = (uint32_t)(par); uint32_t _d;         \
    asm volatile("{\n\t.reg .pred p;\n\t"                                             \
        "mbarrier.try_wait.parity.acquire.cta.shared::cta.b64 p, [%1], %2;\n\t"       \
        "selp.b32 %0, 1, 0, p;\n\t}" : "=r"(_d) : "r"(_m), "r"(_p) : "memory");       \
    if (!_d) {                                                                        \
        asm volatile("{\n\t.reg .pred P1;\n\t"                                        \
            "WL_%=:\n\t"                                                              \
            "mbarrier.try_wait.parity.acquire.cta.shared::cta.b64 P1, [%0], %1, 0x989680;\n\t" \
            "@P1 bra.uni WD_%=;\n\t"                                                  \
            "bra.uni WL_%=;\n\t"                                                      \
            "WD_%=:\n\t}" :: "r"(_m), "r"(_p) : "memory");                            \
    }                                                                                 \
} while (0)
#define TMA_LOAD_2D(smem_addr, tmap_ptr, cx, cy, mb) \
    asm volatile("cp.async.bulk.tensor.2d.shared::cta.global.tile.mbarrier::complete_tx::bytes " \
                 "[%0], [%1, {%2, %3}], [%4];" \
                 :: "r"((uint32_t)(smem_addr)), "l"(tmap_ptr), "r"((int)(cx)), "r"((int)(cy)), \
                    "r"((uint32_t)(mb)) : "memory")

// ===================== device scratch =====================
__device__ int g_top1[NTOK];
__device__ int g_cnt[NEXP];
__device__ int g_cnt2[NEXP];
__device__ int g_off[NEXP];
__device__ int g_perm[NTOK];

__device__ __half g_x16[(size_t)NTOK * DIM];        // x fp16, TOKEN order
__device__ __half g_h[(size_t)PADTOK * HID];        // hidden, fp16, slot order
__device__ __half g_w1[(size_t)NEXP * HID * DIM];   // [e][n(HID)][k(DIM)]
__device__ __half g_w2[(size_t)NEXP * DIM * HID];   // [e][n(DIM)][k(HID)]

// ===================== conv tile body (32x32 transpose fp32->fp16) =====================
__device__ __forceinline__ void conv_tile(const float* __restrict__ src, __half* __restrict__ dst,
                                          int R, int C, int e, int r0, int c0) {
    __shared__ float tile[32][33];
    const int tx = threadIdx.x & 31;
    const int ty = threadIdx.x >> 5;   // 0..7
    const float* s = src + ((size_t)e * R + r0) * C + c0;
#pragma unroll
    for (int j = ty; j < 32; j += 8)
        tile[j][tx] = s[(size_t)j * C + tx];
    __syncthreads();
    __half* o = dst + ((size_t)e * C + c0) * R + r0;
#pragma unroll
    for (int j = ty; j < 32; j += 8)
        o[(size_t)j * R + tx] = __float2half_rn(tile[tx][j]);
}

// ===================== launch 0: gate (+x16) fused with conv_w1 =====================
__global__ __launch_bounds__(256)
void gate_convw1_kernel(const float* __restrict__ x,
                        const float* __restrict__ gw,
                        const float* __restrict__ gb,
                        const float* __restrict__ w1) {
    const int b = blockIdx.x;
    if (b >= 1024) {
        int cb = b - 1024;
        int e  = cb >> 12;
        int r  = cb & 4095;
        int c0 = (r & 127) * 32;
        int r0 = (r >> 7) * 32;
        conv_tile(w1, g_w1, DIM, HID, e, r0, c0);
        return;
    }
    int wid  = threadIdx.x >> 5;
    int lane = threadIdx.x & 31;
    int tok  = b * 8 + wid;
    const float* xr = x + (size_t)tok * DIM;
    __half* xo = g_x16 + (size_t)tok * DIM;
    float acc[NEXP];
#pragma unroll
    for (int e = 0; e < NEXP; e++) acc[e] = 0.f;
    for (int d = lane; d < DIM; d += 32) {
        float xv = xr[d];
        xo[d] = __float2half_rn(xv);
        const float4* g4 = reinterpret_cast<const float4*>(gw + (size_t)d * NEXP);
        float4 g0 = g4[0], g1 = g4[1];
        acc[0] += xv * g0.x; acc[1] += xv * g0.y; acc[2] += xv * g0.z; acc[3] += xv * g0.w;
        acc[4] += xv * g1.x; acc[5] += xv * g1.y; acc[6] += xv * g1.z; acc[7] += xv * g1.w;
    }
#pragma unroll
    for (int e = 0; e < NEXP; e++) {
#pragma unroll
        for (int o = 16; o > 0; o >>= 1) acc[e] += __shfl_xor_sync(0xffffffffu, acc[e], o);
    }
    if (lane == 0) {
        int best = 0; float bv = acc[0] + gb[0];
#pragma unroll
        for (int e = 1; e < NEXP; e++) {
            float v = acc[e] + gb[e];
            if (v > bv) { bv = v; best = e; }
        }
        g_top1[tok] = best;
    }
}

// ===================== launch 1: histogram + scan =====================
__global__ void hist_kernel() {
    __shared__ int cnt[NEXP];
    const int tid = threadIdx.x;
    if (tid < NEXP) cnt[tid] = 0;
    __syncthreads();
    int local[NEXP];
#pragma unroll
    for (int e = 0; e < NEXP; e++) local[e] = 0;
    for (int i = tid; i < NTOK; i += 1024) {
        int v = g_top1[i];
#pragma unroll
        for (int e = 0; e < NEXP; e++) local[e] += (v == e);
    }
#pragma unroll
    for (int e = 0; e < NEXP; e++) {
#pragma unroll
        for (int o = 16; o > 0; o >>= 1) local[e] += __shfl_xor_sync(0xffffffffu, local[e], o);
        if ((tid & 31) == 0 && local[e]) atomicAdd(&cnt[e], local[e]);
    }
    __syncthreads();
    if (tid == 0) {
        int off = 0;
        for (int e = 0; e < NEXP; e++) { g_off[e] = off; g_cnt[e] = cnt[e]; off += cnt[e]; }
    }
    if (tid < NEXP) g_cnt2[tid] = 0;
}

// ===================== launch 2: scatter fused with conv_w2 =====================
__global__ __launch_bounds__(256)
void scatter_convw2_kernel(const float* __restrict__ w2) {
    const int b = blockIdx.x;
    if (b >= 32) {
        int cb = b - 32;
        int e  = cb >> 12;
        int r  = cb & 4095;
        int c0 = (r & 31) * 32;
        int r0 = (r >> 5) * 32;
        conv_tile(w2, g_w2, HID, DIM, e, r0, c0);
        return;
    }
    int n = b * 256 + threadIdx.x;
    int e = g_top1[n];
    int p = atomicAdd(&g_cnt2[e], 1);
    g_perm[g_off[e] + p] = n;
}

// ===================== GEMM geometry (shared) =====================
#define AOFF 0
#define BOFF 16384
#define STAGE 32768
#define NSTAGE 3
#define SMEM_DYN (NSTAGE * STAGE + 1024)   // +1KB slack for 1024B alignment of stage base

// ===================== GEMM1: A via cp.async gather, B via TMA =====================
__global__ __launch_bounds__(128, 2)
void moe_gemm1(const float* __restrict__ bias,
               const __grid_constant__ CUtensorMap bmap) {
    constexpr int KDIM = DIM, NDIM = HID;
    constexpr int NKC  = KDIM / 64;

    const int e  = blockIdx.z;
    const int Me = g_cnt[e];
    const int m0 = blockIdx.y * 128;
    if (m0 >= Me) return;
    const int off = g_off[e];
    const int n0  = blockIdx.x * 128;
    const int brow0 = e * NDIM + n0;

    extern __shared__ __align__(128) char smem[];
    // TMA's SW128 swizzle keys off ABSOLUTE smem address bits [9:7]; the stage
    // base must be 1024B-aligned so HW swizzle == our base-relative ldsm xor.
    const uint32_t sb = (smem_u32(smem) + 1023u) & ~1023u;
    __shared__ int s_perm[128];
    __shared__ alignas(8) uint64_t mbar[NSTAGE];

    const int tid  = threadIdx.x;
    const int lane = tid & 31;
    const int wid  = tid >> 5;
    const int wrow = wid & 1;
    const int wcol = wid >> 1;

    {
        int r = m0 + tid;
        if (r >= Me) r = Me - 1;
        s_perm[tid] = g_perm[off + r];
    }
    if (tid == 0) {
#pragma unroll
        for (int s = 0; s < NSTAGE; s++) MBARRIER_INIT(smem_u32(&mbar[s]), 1);
    }
    __syncthreads();

    auto issue_a = [&](int chunk) {
        const uint32_t base = sb + (chunk % NSTAGE) * STAGE;
        const int k0 = chunk * 64;
#pragma unroll
        for (int w = 0; w < 8; w++) {
            int idx = w * 128 + tid;
            int row = idx >> 3;
            int c8  = idx & 7;
            uint32_t sw = (uint32_t)(row * 128 + ((c8 * 16) ^ ((row & 7) << 4)));
            cp16(base + AOFF + sw, g_x16 + (size_t)s_perm[row] * KDIM + k0 + c8 * 8);
        }
    };
    auto issue_b = [&](int chunk) {          // call from tid==0 only
        const int st = chunk % NSTAGE;
        const uint32_t mb = smem_u32(&mbar[st]);
        MBARRIER_EXPECT_TX(mb, 16384);
        TMA_LOAD_2D(sb + st * STAGE + BOFF, &bmap, chunk * 64, brow0, mb);
    };

    const int sel = lane >> 3;
    const int l7  = lane & 7;
    const uint32_t lxor = (uint32_t)(l7 << 4);
    uint32_t arow[4], brow[4];
#pragma unroll
    for (int mf = 0; mf < 4; mf++)
        arow[mf] = (uint32_t)((wrow * 64 + mf * 16 + (sel & 1) * 8 + l7) * 128);
#pragma unroll
    for (int nb = 0; nb < 4; nb++)
        brow[nb] = (uint32_t)((wcol * 64 + nb * 16 + (sel >> 1) * 8 + l7) * 128);
    const uint32_t acb = (uint32_t)((sel >> 1) * 16);
    const uint32_t bcb = (uint32_t)((sel & 1) * 16);

    float c[4][8][4];
#pragma unroll
    for (int i = 0; i < 4; i++)
#pragma unroll
        for (int j = 0; j < 8; j++)
#pragma unroll
            for (int r = 0; r < 4; r++) c[i][j][r] = 0.f;

    issue_a(0); CP_COMMIT();
    issue_a(1); CP_COMMIT();
    if (tid == 0) { issue_b(0); issue_b(1); }

#pragma unroll 1
    for (int i = 0; i < NKC; i++) {
        if (i < NKC - 1) { CP_WAIT1(); } else { CP_WAIT0(); }
        MBARRIER_WAIT_PARITY(smem_u32(&mbar[i % NSTAGE]), (i / NSTAGE) & 1);
        __syncthreads();
        if (i + 2 < NKC) {
            issue_a(i + 2); CP_COMMIT();
            if (tid == 0) issue_b(i + 2);
        }

        const uint32_t base = sb + (i % NSTAGE) * STAGE;
#pragma unroll
        for (int kk = 0; kk < 4; kk++) {
            const uint32_t colA = (acb + kk * 32) ^ lxor;
            const uint32_t colB = (bcb + kk * 32) ^ lxor;
            uint32_t Af[4][4], Bf[4][4];
#pragma unroll
            for (int mf = 0; mf < 4; mf++)
                ldsm4(Af[mf][0], Af[mf][1], Af[mf][2], Af[mf][3], base + AOFF + arow[mf] + colA);
#pragma unroll
            for (int nb = 0; nb < 4; nb++)
                ldsm4(Bf[nb][0], Bf[nb][1], Bf[nb][2], Bf[nb][3], base + BOFF + brow[nb] + colB);
#pragma unroll
            for (int mf = 0; mf < 4; mf++)
#pragma unroll
                for (int nb = 0; nb < 4; nb++)
#pragma unroll
                    for (int h = 0; h < 2; h++)
                        mma16816(c[mf][nb*2+h][0], c[mf][nb*2+h][1], c[mf][nb*2+h][2], c[mf][nb*2+h][3],
                                 Af[mf][0], Af[mf][1], Af[mf][2], Af[mf][3],
                                 Bf[nb][2*h], Bf[nb][2*h+1]);
        }
    }

    const int gr = lane >> 2;
    const int gc = (lane & 3) * 2;
    const float* bs = bias + (size_t)e * NDIM;
#pragma unroll
    for (int mf = 0; mf < 4; mf++) {
#pragma unroll
        for (int half = 0; half < 2; half++) {
            const int ml = wrow * 64 + mf * 16 + half * 8 + gr;
            if (m0 + ml >= Me) continue;
            const int slot = off + m0 + ml;
#pragma unroll
            for (int nf = 0; nf < 8; nf++) {
                const int n = n0 + wcol * 64 + nf * 8 + gc;
                const float2 bv = *reinterpret_cast<const float2*>(bs + n);
                float v0 = fmaxf(c[mf][nf][half * 2 + 0] + bv.x, 0.f);
                float v1 = fmaxf(c[mf][nf][half * 2 + 1] + bv.y, 0.f);
                *reinterpret_cast<__half2*>(g_h + (size_t)slot * HID + n) =
                    __half2(__float2half_rn(v0), __float2half_rn(v1));
            }
        }
    }
}

// ===================== GEMM2: A and B via TMA =====================
__global__ __launch_bounds__(128, 2)
void moe_gemm2(const float* __restrict__ bias,
               const float* __restrict__ x,
               float* __restrict__ out,
               const __grid_constant__ CUtensorMap amap,
               const __grid_constant__ CUtensorMap bmap) {
    constexpr int KDIM = HID, NDIM = DIM;
    constexpr int NKC  = KDIM / 64;

    const int e  = blockIdx.z;
    const int Me = g_cnt[e];
    const int m0 = blockIdx.y * 128;
    if (m0 >= Me) return;
    const int off = g_off[e];
    const int n0  = blockIdx.x * 128;
    const int brow0 = e * NDIM + n0;

    extern __shared__ __align__(128) char smem[];
    const uint32_t sb = (smem_u32(smem) + 1023u) & ~1023u;   // 1024B-align for TMA SW128
    __shared__ int s_perm[128];
    __shared__ alignas(8) uint64_t mbar[NSTAGE];

    const int tid  = threadIdx.x;
    const int lane = tid & 31;
    const int wid  = tid >> 5;
    const int wrow = wid & 1;
    const int wcol = wid >> 1;

    {
        int r = m0 + tid;
        if (r >= Me) r = Me - 1;
        s_perm[tid] = g_perm[off + r];
    }
    if (tid == 0) {
#pragma unroll
        for (int s = 0; s < NSTAGE; s++) MBARRIER_INIT(smem_u32(&mbar[s]), 1);
    }
    __syncthreads();

    auto issue_ab = [&](int chunk) {         // tid==0 only
        const int st = chunk % NSTAGE;
        const uint32_t mb = smem_u32(&mbar[st]);
        MBARRIER_EXPECT_TX(mb, 32768);
        TMA_LOAD_2D(sb + st * STAGE + AOFF, &amap, chunk * 64, off + m0, mb);
        TMA_LOAD_2D(sb + st * STAGE + BOFF, &bmap, chunk * 64, brow0, mb);
    };

    const int sel = lane >> 3;
    const int l7  = lane & 7;
    const uint32_t lxor = (uint32_t)(l7 << 4);
    uint32_t arow[4], brow[4];
#pragma unroll
    for (int mf = 0; mf < 4; mf++)
        arow[mf] = (uint32_t)((wrow * 64 + mf * 16 + (sel & 1) * 8 + l7) * 128);
#pragma unroll
    for (int nb = 0; nb < 4; nb++)
        brow[nb] = (uint32_t)((wcol * 64 + nb * 16 + (sel >> 1) * 8 + l7) * 128);
    const uint32_t acb = (uint32_t)((sel >> 1) * 16);
    const uint32_t bcb = (uint32_t)((sel & 1) * 16);

    float c[4][8][4];
#pragma unroll
    for (int i = 0; i < 4; i++)
#pragma unroll
        for (int j = 0; j < 8; j++)
#pragma unroll
            for (int r = 0; r < 4; r++) c[i][j][r] = 0.f;

    if (tid == 0) { issue_ab(0); issue_ab(1); }

#pragma unroll 1
    for (int i = 0; i < NKC; i++) {
        MBARRIER_WAIT_PARITY(smem_u32(&mbar[i % NSTAGE]), (i / NSTAGE) & 1);
        __syncthreads();
        if (i + 2 < NKC && tid == 0) issue_ab(i + 2);

        const uint32_t base = sb + (i % NSTAGE) * STAGE;
#pragma unroll
        for (int kk = 0; kk < 4; kk++) {
            const uint32_t colA = (acb + kk * 32) ^ lxor;
            const uint32_t colB = (bcb + kk * 32) ^ lxor;
            uint32_t Af[4][4], Bf[4][4];
#pragma unroll
            for (int mf = 0; mf < 4; mf++)
                ldsm4(Af[mf][0], Af[mf][1], Af[mf][2], Af[mf][3], base + AOFF + arow[mf] + colA);
#pragma unroll
            for (int nb = 0; nb < 4; nb++)
                ldsm4(Bf[nb][0], Bf[nb][1], Bf[nb][2], Bf[nb][3], base + BOFF + brow[nb] + colB);
#pragma unroll
            for (int mf = 0; mf < 4; mf++)
#pragma unroll
                for (int nb = 0; nb < 4; nb++)
#pragma unroll
                    for (int h = 0; h < 2; h++)
                        mma16816(c[mf][nb*2+h][0], c[mf][nb*2+h][1], c[mf][nb*2+h][2], c[mf][nb*2+h][3],
                                 Af[mf][0], Af[mf][1], Af[mf][2], Af[mf][3],
                                 Bf[nb][2*h], Bf[nb][2*h+1]);
        }
    }

    const int gr = lane >> 2;
    const int gc = (lane & 3) * 2;
    const float* bs = bias + (size_t)e * NDIM;
#pragma unroll
    for (int mf = 0; mf < 4; mf++) {
#pragma unroll
        for (int half = 0; half < 2; half++) {
            const int ml = wrow * 64 + mf * 16 + half * 8 + gr;
            if (m0 + ml >= Me) continue;
            const int tok = s_perm[ml];
#pragma unroll
            for (int nf = 0; nf < 8; nf++) {
                const int n = n0 + wcol * 64 + nf * 8 + gc;
                const float2 bv = *reinterpret_cast<const float2*>(bs + n);
                const float2 xv = *reinterpret_cast<const float2*>(x + (size_t)tok * DIM + n);
                float2 ov = make_float2(c[mf][nf][half * 2 + 0] + bv.x + xv.x,
                                        c[mf][nf][half * 2 + 1] + bv.y + xv.y);
                *reinterpret_cast<float2*>(out + (size_t)tok * DIM + n) = ov;
            }
        }
    }
}

// ===================== host: tensor map creation =====================
typedef CUresult (*PFN_cuTensorMapEncodeTiled)(
    CUtensorMap*, CUtensorMapDataType, cuuint32_t, void*,
    const cuuint64_t*, const cuuint64_t*, const cuuint32_t*, const cuuint32_t*,
    CUtensorMapInterleave, CUtensorMapSwizzle, CUtensorMapL2promotion, CUtensorMapFloatOOBfill);

static void encode_fp16_2d(PFN_cuTensorMapEncodeTiled enc, CUtensorMap* m,
                           void* gaddr, unsigned long long inner, unsigned long long rows) {
    cuuint64_t dims[2]    = {(cuuint64_t)inner, (cuuint64_t)rows};
    cuuint64_t strides[1] = {(cuuint64_t)inner * 2};
    cuuint32_t box[2]     = {64, 128};
    cuuint32_t es[2]      = {1, 1};
    enc(m, CU_TENSOR_MAP_DATA_TYPE_FLOAT16, 2, gaddr, dims, strides, box, es,
        CU_TENSOR_MAP_INTERLEAVE_NONE, CU_TENSOR_MAP_SWIZZLE_128B,
        CU_TENSOR_MAP_L2_PROMOTION_L2_128B, CU_TENSOR_MAP_FLOAT_OOB_FILL_NONE);
}

extern "C" void kernel_launch(void* const* d_in, const int* in_sizes, int n_in,
                              void* d_out, int out_size) {
    const float* x  = (const float*)d_in[0];
    const float* gw = (const float*)d_in[1];
    const float* gb = (const float*)d_in[2];
    const float* w1 = (const float*)d_in[3];
    const float* b1 = (const float*)d_in[4];
    const float* w2 = (const float*)d_in[5];
    const float* b2 = (const float*)d_in[6];
    float* out = (float*)d_out;

    void* encFn = nullptr;
    cudaDriverEntryPointQueryResult qr;
    cudaGetDriverEntryPoint("cuTensorMapEncodeTiled", &encFn, cudaEnableDefault, &qr);
    PFN_cuTensorMapEncodeTiled enc = (PFN_cuTensorMapEncodeTiled)encFn;

    void *p_w1, *p_w2, *p_h;
    cudaGetSymbolAddress(&p_w1, g_w1);
    cudaGetSymbolAddress(&p_w2, g_w2);
    cudaGetSymbolAddress(&p_h,  g_h);

    CUtensorMap m_w1, m_w2, m_h;
    encode_fp16_2d(enc, &m_w1, p_w1, DIM, (unsigned long long)NEXP * HID);
    encode_fp16_2d(enc, &m_w2, p_w2, HID, (unsigned long long)NEXP * DIM);
    encode_fp16_2d(enc, &m_h,  p_h,  HID, (unsigned long long)PADTOK);

    cudaFuncSetAttribute(moe_gemm1, cudaFuncAttributeMaxDynamicSharedMemorySize, SMEM_DYN);
    cudaFuncSetAttribute(moe_gemm2, cudaFuncAttributeMaxDynamicSharedMemorySize, SMEM_DYN);

    gate_convw1_kernel<<<1024 + 32768, 256>>>(x, gw, gb, w1);
    hist_kernel<<<1, 1024>>>();
    scatter_convw2_kernel<<<32 + 32768, 256>>>(w2);
    moe_gemm1<<<dim3(HID / 128, NTOK / 128, NEXP), 128, SMEM_DYN>>>(b1, m_w1);
    moe_gemm2<<<dim3(DIM / 128, NTOK / 128, NEXP), 128, SMEM_DYN>>>(b2, x, out, m_h, m_w2);
}